// round 2
// baseline (speedup 1.0000x reference)
#include <cuda_runtime.h>

#define AD 512
#define BB 16
#define HH 8
#define CROSS_C 359   // A - int(A*0.3) = 512 - 153

// ---------------- scratch (static device globals; no allocs) ----------------
__device__ float g_Qp[BB * AD * AD];
__device__ float g_Kp[BB * AD * AD];
__device__ float g_am0[BB * AD * AD];
__device__ float g_Vp[BB * AD];
__device__ float g_att[BB * HH * AD];
__device__ int g_mutate;
__device__ unsigned g_km[2];
__device__ unsigned g_r1[BB * HH];
__device__ unsigned g_r2[BB * HH];

// ---------------- threefry2x32 (20 rounds, JAX-compatible) ----------------
__device__ __forceinline__ void tf2x32(unsigned k0, unsigned k1,
                                       unsigned x0, unsigned x1,
                                       unsigned &o0, unsigned &o1) {
    unsigned k2 = k0 ^ k1 ^ 0x1BD11BDAu;
    x0 += k0; x1 += k1;
#define TFR(r) { x0 += x1; x1 = __funnelshift_l(x1, x1, r); x1 ^= x0; }
    TFR(13) TFR(15) TFR(26) TFR(6)   x0 += k1; x1 += k2 + 1u;
    TFR(17) TFR(29) TFR(16) TFR(24)  x0 += k2; x1 += k0 + 2u;
    TFR(13) TFR(15) TFR(26) TFR(6)   x0 += k0; x1 += k1 + 3u;
    TFR(17) TFR(29) TFR(16) TFR(24)  x0 += k1; x1 += k2 + 4u;
    TFR(13) TFR(15) TFR(26) TFR(6)   x0 += k2; x1 += k0 + 5u;
#undef TFR
    o0 = x0; o1 = x1;
}

// uniform [0,1) from 32 random bits, JAX style
__device__ __forceinline__ float bits_to_unit(unsigned bits) {
    return __uint_as_float((bits >> 9) | 0x3f800000u) - 1.0f;
}

// ---------------- RNG init: branch flag, mutation key, crossover indices ----
// JAX partitionable threefry:
//   split(key, n): subkey i = threefry2x32(key, (0, i))   (both output words)
//   random_bits32 at flat index f: o0 ^ o1 of threefry2x32(key, (hi(f), lo(f)))
__global__ void rng_init() {
    int tid = threadIdx.x;
    unsigned kp0, kp1, km0, km1, ka0, ka1, kb0, kb1;
    // base key = key(42) = (0, 42); split into 4: kp, km, kr1, kr2
    tf2x32(0u, 42u, 0u, 0u, kp0, kp1);
    tf2x32(0u, 42u, 0u, 1u, km0, km1);
    tf2x32(0u, 42u, 0u, 2u, ka0, ka1);
    tf2x32(0u, 42u, 0u, 3u, kb0, kb1);
    if (tid == 0) {
        unsigned b0, b1;
        tf2x32(kp0, kp1, 0u, 0u, b0, b1);
        float p = bits_to_unit(b0 ^ b1);
        g_mutate = (p <= 0.6f) ? 1 : 0;
        g_km[0] = km0; g_km[1] = km1;
    }
    if (tid < BB * HH) {
        // randint(key,(16,8),0,512): multiplier = (2^16 % 512)^2 % 512 = 0
        // -> result = lower_bits % 512, lower_bits drawn with 2nd key of split(key)
        unsigned s0, s1, l0, l1;
        tf2x32(ka0, ka1, 0u, 1u, s0, s1);               // k2 of split(kr1)
        tf2x32(s0, s1, 0u, (unsigned)tid, l0, l1);
        g_r1[tid] = (l0 ^ l1) & (AD - 1u);
        tf2x32(kb0, kb1, 0u, 1u, s0, s1);               // k2 of split(kr2)
        tf2x32(s0, s1, 0u, (unsigned)tid, l0, l1);
        g_r2[tid] = (l0 ^ l1) & (AD - 1u);
    }
}

// ---------------- projection GEMM: C[b,j,i] = sum_t X[b,j,t]*W[i,t] + bias[i]
// 128x128 tile, BK=8, 256 threads, 8x8 per thread
__global__ __launch_bounds__(256) void gemm_proj(const float* __restrict__ X,
                                                 const float* __restrict__ W,
                                                 const float* __restrict__ bias,
                                                 int which) {
    float* C = which ? g_Kp : g_Qp;
    __shared__ float As[8][128];   // As[t][j]
    __shared__ float Ws[8][128];   // Ws[t][i]
    int b = blockIdx.z;
    int i0 = blockIdx.x * 128, j0 = blockIdx.y * 128;
    const float* Xb = X + b * AD * AD;
    int tid = threadIdx.x;
    int lj = tid >> 1;
    int lt = (tid & 1) << 2;
    int ty = tid >> 4, tx = tid & 15;
    float acc[8][8];
#pragma unroll
    for (int r = 0; r < 8; r++)
#pragma unroll
        for (int c = 0; c < 8; c++) acc[r][c] = 0.f;

    for (int t0 = 0; t0 < AD; t0 += 8) {
        float4 av = *(const float4*)(Xb + (j0 + lj) * AD + t0 + lt);
        float4 wv = *(const float4*)(W + (i0 + lj) * AD + t0 + lt);
        __syncthreads();
        As[lt + 0][lj] = av.x; As[lt + 1][lj] = av.y;
        As[lt + 2][lj] = av.z; As[lt + 3][lj] = av.w;
        Ws[lt + 0][lj] = wv.x; Ws[lt + 1][lj] = wv.y;
        Ws[lt + 2][lj] = wv.z; Ws[lt + 3][lj] = wv.w;
        __syncthreads();
#pragma unroll
        for (int t = 0; t < 8; t++) {
            float a[8], w[8];
            *(float4*)(a)     = *(const float4*)(&As[t][ty * 8]);
            *(float4*)(a + 4) = *(const float4*)(&As[t][ty * 8 + 4]);
            *(float4*)(w)     = *(const float4*)(&Ws[t][tx * 8]);
            *(float4*)(w + 4) = *(const float4*)(&Ws[t][tx * 8 + 4]);
#pragma unroll
            for (int r = 0; r < 8; r++)
#pragma unroll
                for (int c = 0; c < 8; c++) acc[r][c] += a[r] * w[c];
        }
    }
    float bi[8];
#pragma unroll
    for (int c = 0; c < 8; c++) bi[c] = bias[i0 + tx * 8 + c];
    float* Cb = C + b * AD * AD;
#pragma unroll
    for (int r = 0; r < 8; r++) {
        int j = j0 + ty * 8 + r;
        float4 v0, v1;
        v0.x = acc[r][0] + bi[0]; v0.y = acc[r][1] + bi[1];
        v0.z = acc[r][2] + bi[2]; v0.w = acc[r][3] + bi[3];
        v1.x = acc[r][4] + bi[4]; v1.y = acc[r][5] + bi[5];
        v1.z = acc[r][6] + bi[6]; v1.w = acc[r][7] + bi[7];
        *(float4*)(Cb + j * AD + i0 + tx * 8)     = v0;
        *(float4*)(Cb + j * AD + i0 + tx * 8 + 4) = v1;
    }
}

// ---------------- scores GEMM: am0[b,i,k] = (1/sqrt8) * sum_j Qp[b,j,i]*Kp[b,j,k]
__global__ __launch_bounds__(256) void gemm_scores() {
    __shared__ float As[8][128];   // As[j][i]
    __shared__ float Bs[8][128];   // Bs[j][k]
    int b = blockIdx.z;
    int i0 = blockIdx.y * 128, k0 = blockIdx.x * 128;
    const float* Qb = g_Qp + b * AD * AD;
    const float* Kb = g_Kp + b * AD * AD;
    int tid = threadIdx.x;
    int lr = tid >> 5;
    int lc = (tid & 31) << 2;
    int ty = tid >> 4, tx = tid & 15;
    float acc[8][8];
#pragma unroll
    for (int r = 0; r < 8; r++)
#pragma unroll
        for (int c = 0; c < 8; c++) acc[r][c] = 0.f;

    for (int jj = 0; jj < AD; jj += 8) {
        float4 qv = *(const float4*)(Qb + (jj + lr) * AD + i0 + lc);
        float4 kv = *(const float4*)(Kb + (jj + lr) * AD + k0 + lc);
        __syncthreads();
        *(float4*)(&As[lr][lc]) = qv;
        *(float4*)(&Bs[lr][lc]) = kv;
        __syncthreads();
#pragma unroll
        for (int t = 0; t < 8; t++) {
            float a[8], w[8];
            *(float4*)(a)     = *(const float4*)(&As[t][ty * 8]);
            *(float4*)(a + 4) = *(const float4*)(&As[t][ty * 8 + 4]);
            *(float4*)(w)     = *(const float4*)(&Bs[t][tx * 8]);
            *(float4*)(w + 4) = *(const float4*)(&Bs[t][tx * 8 + 4]);
#pragma unroll
            for (int r = 0; r < 8; r++)
#pragma unroll
                for (int c = 0; c < 8; c++) acc[r][c] += a[r] * w[c];
        }
    }
    const float scale = 0.3535533905932738f;  // 1/sqrt(8)
    float* Cb = g_am0 + b * AD * AD;
#pragma unroll
    for (int r = 0; r < 8; r++) {
        int i = i0 + ty * 8 + r;
        float4 v0, v1;
        v0.x = acc[r][0] * scale; v0.y = acc[r][1] * scale;
        v0.z = acc[r][2] * scale; v0.w = acc[r][3] * scale;
        v1.x = acc[r][4] * scale; v1.y = acc[r][5] * scale;
        v1.z = acc[r][6] * scale; v1.w = acc[r][7] * scale;
        *(float4*)(Cb + i * AD + k0 + tx * 8)     = v0;
        *(float4*)(Cb + i * AD + k0 + tx * 8 + 4) = v1;
    }
}

// ---------------- Vp = V @ WV^T + b  (16x512, tiny) ----------------
__global__ __launch_bounds__(256) void vproj(const float* __restrict__ V,
                                             const float* __restrict__ Ww,
                                             const float* __restrict__ Wb) {
    int b = blockIdx.x;
    int wid = threadIdx.x >> 5, lane = threadIdx.x & 31;
    const float* vr = V + b * AD;
#pragma unroll
    for (int ii = 0; ii < 4; ii++) {
        int i = blockIdx.y * 32 + wid * 4 + ii;
        const float* wr = Ww + i * AD;
        float s = 0.f;
        for (int t = lane; t < AD; t += 32) s += vr[t] * wr[t];
#pragma unroll
        for (int o = 16; o; o >>= 1) s += __shfl_xor_sync(~0u, s, o);
        if (lane == 0) g_Vp[b * AD + i] = s + Wb[i];
    }
}

// ---------------- fused mutate/crossover + softmax + attn·Vp ----------------
// one block (128 threads) per (b,h,i) row of the broadcast score matrix
__global__ __launch_bounds__(128) void attn_kernel() {
    int row = blockIdx.x;                 // (b*8+h)*512 + i
    int i = row & (AD - 1);
    int h = (row >> 9) & (HH - 1);
    int b = row >> 12;
    int tid = threadIdx.x;
    const float* am = g_am0 + b * AD * AD;
    float v[4];

    if (g_mutate) {
        unsigned km0 = g_km[0], km1 = g_km[1];
        unsigned base = ((unsigned)row) << 9;   // flat index of (b,h,i,0) in (B,H,A,A)
#pragma unroll
        for (int q = 0; q < 4; q++) {
            int k = tid + q * 128;
            unsigned o0, o1;
            tf2x32(km0, km1, 0u, base + (unsigned)k, o0, o1);
            float u = bits_to_unit(o0 ^ o1);
            const float df = 1.3f - 0.7f;
            float m = fmaxf(0.7f, fmaf(u, df, 0.7f));
            v[q] = am[i * AD + k] * m;
        }
    } else {
        int r1 = (int)g_r1[b * HH + h], r2 = (int)g_r2[b * HH + h];
#pragma unroll
        for (int q = 0; q < 4; q++) {
            int k = tid + q * 128;
            int src = i;
            if (k >= CROSS_C) {
                if (i == r1) src = r2;
                else if (i == r2) src = r1;
            }
            v[q] = am[src * AD + k];
        }
    }

    // block max
    float mx = fmaxf(fmaxf(v[0], v[1]), fmaxf(v[2], v[3]));
#pragma unroll
    for (int o = 16; o; o >>= 1) mx = fmaxf(mx, __shfl_xor_sync(~0u, mx, o));
    __shared__ float smx[4], ssum[4], sdot[4];
    int wid = tid >> 5, lane = tid & 31;
    if (lane == 0) smx[wid] = mx;
    __syncthreads();
    mx = fmaxf(fmaxf(smx[0], smx[1]), fmaxf(smx[2], smx[3]));

    // exp-sum and dot with Vp in one pass
    float s = 0.f, d = 0.f;
    const float* Vb = g_Vp + b * AD;
#pragma unroll
    for (int q = 0; q < 4; q++) {
        float e = expf(v[q] - mx);
        s += e;
        d += e * Vb[tid + q * 128];
    }
#pragma unroll
    for (int o = 16; o; o >>= 1) {
        s += __shfl_xor_sync(~0u, s, o);
        d += __shfl_xor_sync(~0u, d, o);
    }
    if (lane == 0) { ssum[wid] = s; sdot[wid] = d; }
    __syncthreads();
    if (tid == 0) {
        float S = ssum[0] + ssum[1] + ssum[2] + ssum[3];
        float D = sdot[0] + sdot[1] + sdot[2] + sdot[3];
        g_att[b * (HH * AD) + h * AD + i] = D / S;
    }
}

// ---------------- out = att(16,4096) @ WO_w(512,4096)^T + WO_b ----------------
__global__ __launch_bounds__(256) void outproj(const float* __restrict__ Ww,
                                               const float* __restrict__ Wb,
                                               float* __restrict__ out) {
    __shared__ float arow[HH * AD];   // 4096 floats = 16 KB
    int b = blockIdx.x;
    for (int m = threadIdx.x; m < HH * AD; m += 256) arow[m] = g_att[b * HH * AD + m];
    __syncthreads();
    int wid = threadIdx.x >> 5, lane = threadIdx.x & 31;
    for (int n = wid; n < AD; n += 8) {
        const float* wr = Ww + n * (HH * AD);
        float s = 0.f;
        for (int m = lane; m < HH * AD; m += 32) s += arow[m] * wr[m];
#pragma unroll
        for (int o = 16; o; o >>= 1) s += __shfl_xor_sync(~0u, s, o);
        if (lane == 0) out[b * AD + n] = s + Wb[n];
    }
}

// ---------------- launch ----------------
extern "C" void kernel_launch(void* const* d_in, const int* in_sizes, int n_in,
                              void* d_out, int out_size) {
    const float* Q   = (const float*)d_in[0];
    const float* K   = (const float*)d_in[1];
    const float* V   = (const float*)d_in[2];
    const float* WQw = (const float*)d_in[3];
    const float* WQb = (const float*)d_in[4];
    const float* WKw = (const float*)d_in[5];
    const float* WKb = (const float*)d_in[6];
    const float* WVw = (const float*)d_in[7];
    const float* WVb = (const float*)d_in[8];
    const float* WOw = (const float*)d_in[9];
    const float* WOb = (const float*)d_in[10];
    float* out = (float*)d_out;

    rng_init<<<1, 128>>>();
    dim3 g(4, 4, BB);
    gemm_proj<<<g, 256>>>(Q, WQw, WQb, 0);
    gemm_proj<<<g, 256>>>(K, WKw, WKb, 1);
    vproj<<<dim3(BB, 16), 256>>>(V, WVw, WVb);
    gemm_scores<<<g, 256>>>();
    attn_kernel<<<BB * HH * AD, 128>>>();
    outproj<<<BB, 256>>>(WOw, WOb, out);
}

// round 3
// speedup vs baseline: 2.0172x; 2.0172x over previous
#include <cuda_runtime.h>

#define AD 512
#define BB 16
#define HH 8
#define CROSS_C 359   // A - int(A*0.3) = 512 - 153

// ---------------- scratch (static device globals; no allocs) ----------------
__device__ float g_QpT[BB * AD * AD];   // QpT[b][i][j] = Qp[b][j][i]
__device__ float g_KpT[BB * AD * AD];   // KpT[b][k][j] = Kp[b][j][k]
__device__ float g_am0[BB * AD * AD];   // am0[b][i][k]
__device__ float g_Vp[BB * AD];
__device__ float g_att[BB * HH * AD];
__device__ int g_mutate;
__device__ unsigned g_km[2];
__device__ unsigned g_r1[BB * HH];
__device__ unsigned g_r2[BB * HH];

// ---------------- threefry2x32 (20 rounds, JAX-compatible) ----------------
__device__ __forceinline__ void tf2x32(unsigned k0, unsigned k1,
                                       unsigned x0, unsigned x1,
                                       unsigned &o0, unsigned &o1) {
    unsigned k2 = k0 ^ k1 ^ 0x1BD11BDAu;
    x0 += k0; x1 += k1;
#define TFR(r) { x0 += x1; x1 = __funnelshift_l(x1, x1, r); x1 ^= x0; }
    TFR(13) TFR(15) TFR(26) TFR(6)   x0 += k1; x1 += k2 + 1u;
    TFR(17) TFR(29) TFR(16) TFR(24)  x0 += k2; x1 += k0 + 2u;
    TFR(13) TFR(15) TFR(26) TFR(6)   x0 += k0; x1 += k1 + 3u;
    TFR(17) TFR(29) TFR(16) TFR(24)  x0 += k1; x1 += k2 + 4u;
    TFR(13) TFR(15) TFR(26) TFR(6)   x0 += k2; x1 += k0 + 5u;
#undef TFR
    o0 = x0; o1 = x1;
}

__device__ __forceinline__ float bits_to_unit(unsigned bits) {
    return __uint_as_float((bits >> 9) | 0x3f800000u) - 1.0f;
}

// ---------------- RNG init (bit-exact vs JAX partitionable threefry) --------
__global__ void rng_init() {
    int tid = threadIdx.x;
    unsigned kp0, kp1, km0, km1, ka0, ka1, kb0, kb1;
    tf2x32(0u, 42u, 0u, 0u, kp0, kp1);
    tf2x32(0u, 42u, 0u, 1u, km0, km1);
    tf2x32(0u, 42u, 0u, 2u, ka0, ka1);
    tf2x32(0u, 42u, 0u, 3u, kb0, kb1);
    if (tid == 0) {
        unsigned b0, b1;
        tf2x32(kp0, kp1, 0u, 0u, b0, b1);
        float p = bits_to_unit(b0 ^ b1);
        g_mutate = (p <= 0.6f) ? 1 : 0;
        g_km[0] = km0; g_km[1] = km1;
    }
    if (tid < BB * HH) {
        unsigned s0, s1, l0, l1;
        tf2x32(ka0, ka1, 0u, 1u, s0, s1);
        tf2x32(s0, s1, 0u, (unsigned)tid, l0, l1);
        g_r1[tid] = (l0 ^ l1) & (AD - 1u);
        tf2x32(kb0, kb1, 0u, 1u, s0, s1);
        tf2x32(s0, s1, 0u, (unsigned)tid, l0, l1);
        g_r2[tid] = (l0 ^ l1) & (AD - 1u);
    }
}

// ---------------- tf32 helpers ----------------
__device__ __forceinline__ void split_tf32(float x, unsigned &hi, unsigned &lo) {
    unsigned h;
    asm("cvt.rna.tf32.f32 %0, %1;" : "=r"(h) : "f"(x));
    float r = x - __uint_as_float(h);
    unsigned l;
    asm("cvt.rna.tf32.f32 %0, %1;" : "=r"(l) : "f"(r));
    hi = h; lo = l;
}

__device__ __forceinline__ void mma_tf32(float* c, const unsigned* a, const unsigned* b) {
    asm volatile(
        "mma.sync.aligned.m16n8k8.row.col.f32.tf32.tf32.f32 "
        "{%0,%1,%2,%3}, {%4,%5,%6,%7}, {%8,%9}, {%0,%1,%2,%3};"
        : "+f"(c[0]), "+f"(c[1]), "+f"(c[2]), "+f"(c[3])
        : "r"(a[0]), "r"(a[1]), "r"(a[2]), "r"(a[3]), "r"(b[0]), "r"(b[1]));
}

#define CP16(dst_s, src_g) \
    asm volatile("cp.async.cg.shared.global [%0], [%1], 16;\n" :: "r"(dst_s), "l"(src_g))
#define CP_COMMIT asm volatile("cp.async.commit_group;\n" ::)
#define CP_WAIT(n) asm volatile("cp.async.wait_group %0;\n" :: "n"(n))

__device__ __forceinline__ unsigned saddr(const void* p) {
    return (unsigned)__cvta_generic_to_shared(p);
}

// ---------------- TN GEMM core: C[m][n] = scale * sum_k A[m][k]*B[n][k] + bias[m]
// BM=BN=128, BK=16, 256 threads (8 warps, 4x2), warp tile 32x64, 3xTF32 mma
__device__ __forceinline__ void gemm_tn_core(const float* __restrict__ A,
                                             const float* __restrict__ B,
                                             float* __restrict__ C,
                                             const float* __restrict__ bias,
                                             float scale) {
    __shared__ float As[2][128][20];
    __shared__ float Bs[2][128][20];
    int tid = threadIdx.x;
    int lane = tid & 31, wid = tid >> 5;
    int wm = wid & 3, wn = wid >> 2;
    int m0 = blockIdx.y * 128, n0 = blockIdx.x * 128;
    int qr = lane >> 2, qc = lane & 3;

    float acc[2][8][4];
#pragma unroll
    for (int mi = 0; mi < 2; mi++)
#pragma unroll
        for (int ni = 0; ni < 8; ni++)
#pragma unroll
            for (int e = 0; e < 4; e++) acc[mi][ni][e] = 0.f;

    int lr = tid >> 2;
    int lc = (tid & 3) * 4;
    const float* Ag = A + (size_t)(m0 + lr) * AD + lc;
    const float* Bg = B + (size_t)(n0 + lr) * AD + lc;

    // prefetch stage 0
    CP16(saddr(&As[0][lr][lc]),      Ag);
    CP16(saddr(&As[0][lr + 64][lc]), Ag + 64 * AD);
    CP16(saddr(&Bs[0][lr][lc]),      Bg);
    CP16(saddr(&Bs[0][lr + 64][lc]), Bg + 64 * AD);
    CP_COMMIT;

    const int NIT = AD / 16;
    for (int it = 0; it < NIT; ++it) {
        int s = it & 1;
        if (it + 1 < NIT) {
            const float* Ap = Ag + (it + 1) * 16;
            const float* Bp = Bg + (it + 1) * 16;
            CP16(saddr(&As[s ^ 1][lr][lc]),      Ap);
            CP16(saddr(&As[s ^ 1][lr + 64][lc]), Ap + 64 * AD);
            CP16(saddr(&Bs[s ^ 1][lr][lc]),      Bp);
            CP16(saddr(&Bs[s ^ 1][lr + 64][lc]), Bp + 64 * AD);
            CP_COMMIT;
            CP_WAIT(1);
        } else {
            CP_WAIT(0);
        }
        __syncthreads();

#pragma unroll
        for (int kk = 0; kk < 16; kk += 8) {
            unsigned ah[2][4], al[2][4];
#pragma unroll
            for (int mi = 0; mi < 2; mi++)
#pragma unroll
                for (int e = 0; e < 4; e++) {
                    float x = As[s][wm * 32 + mi * 16 + qr + (e & 1) * 8]
                                 [kk + qc + (e >> 1) * 4];
                    split_tf32(x, ah[mi][e], al[mi][e]);
                }
#pragma unroll
            for (int half = 0; half < 2; half++) {
                unsigned bh[4][2], bl[4][2];
#pragma unroll
                for (int ni = 0; ni < 4; ni++)
#pragma unroll
                    for (int e = 0; e < 2; e++) {
                        float x = Bs[s][wn * 64 + (half * 4 + ni) * 8 + qr]
                                     [kk + qc + e * 4];
                        split_tf32(x, bh[ni][e], bl[ni][e]);
                    }
#pragma unroll
                for (int mi = 0; mi < 2; mi++)
#pragma unroll
                    for (int ni = 0; ni < 4; ni++) {
                        float* c = acc[mi][half * 4 + ni];
                        mma_tf32(c, ah[mi], bh[ni]);
                        mma_tf32(c, ah[mi], bl[ni]);
                        mma_tf32(c, al[mi], bh[ni]);
                    }
            }
        }
        __syncthreads();
    }

    // epilogue
#pragma unroll
    for (int mi = 0; mi < 2; mi++) {
        int r0 = m0 + wm * 32 + mi * 16 + qr;
        float b0 = 0.f, b1 = 0.f;
        if (bias) { b0 = __ldg(bias + r0); b1 = __ldg(bias + r0 + 8); }
#pragma unroll
        for (int ni = 0; ni < 8; ni++) {
            int c0 = n0 + wn * 64 + ni * 8 + qc * 2;
            float2 v0, v1;
            v0.x = acc[mi][ni][0] * scale + b0;
            v0.y = acc[mi][ni][1] * scale + b0;
            v1.x = acc[mi][ni][2] * scale + b1;
            v1.y = acc[mi][ni][3] * scale + b1;
            *(float2*)&C[(size_t)r0 * AD + c0] = v0;
            *(float2*)&C[(size_t)(r0 + 8) * AD + c0] = v1;
        }
    }
}

// merged Q/K projection: QpT[i][j] = sum_t W[i,t]*X[j,t] + bias[i]
__global__ __launch_bounds__(256, 2) void proj_kernel(
    const float* __restrict__ Q, const float* __restrict__ K,
    const float* __restrict__ WQw, const float* __restrict__ WQb,
    const float* __restrict__ WKw, const float* __restrict__ WKb) {
    int z = blockIdx.z;
    int b = z & (BB - 1);
    int sel = z >> 4;
    const float* A = sel ? WKw : WQw;
    const float* X = (sel ? K : Q) + (size_t)b * AD * AD;
    float* C = (sel ? g_KpT : g_QpT) + (size_t)b * AD * AD;
    const float* bias = sel ? WKb : WQb;
    gemm_tn_core(A, X, C, bias, 1.0f);
}

// scores: am0[i][k] = (1/sqrt8) * sum_j QpT[i][j]*KpT[k][j]
__global__ __launch_bounds__(256, 2) void scores_kernel() {
    int b = blockIdx.z;
    gemm_tn_core(g_QpT + (size_t)b * AD * AD, g_KpT + (size_t)b * AD * AD,
                 g_am0 + (size_t)b * AD * AD, nullptr, 0.3535533905932738f);
}

// ---------------- Vp = V @ WV^T + b  (16x512, tiny) ----------------
__global__ __launch_bounds__(256) void vproj(const float* __restrict__ V,
                                             const float* __restrict__ Ww,
                                             const float* __restrict__ Wb) {
    int b = blockIdx.x;
    int wid = threadIdx.x >> 5, lane = threadIdx.x & 31;
    const float* vr = V + b * AD;
#pragma unroll
    for (int ii = 0; ii < 4; ii++) {
        int i = blockIdx.y * 32 + wid * 4 + ii;
        const float* wr = Ww + (size_t)i * AD;
        float s = 0.f;
        for (int t = lane; t < AD; t += 32) s += vr[t] * wr[t];
#pragma unroll
        for (int o = 16; o; o >>= 1) s += __shfl_xor_sync(~0u, s, o);
        if (lane == 0) g_Vp[b * AD + i] = s + Wb[i];
    }
}

// ---------------- fused mutate/crossover + softmax + attn·Vp ----------------
__global__ __launch_bounds__(128) void attn_kernel() {
    int row = blockIdx.x;                 // (b*8+h)*512 + i
    int i = row & (AD - 1);
    int h = (row >> 9) & (HH - 1);
    int b = row >> 12;
    int tid = threadIdx.x;
    const float* am = g_am0 + (size_t)b * AD * AD;
    float v[4];

    if (g_mutate) {
        unsigned km0 = g_km[0], km1 = g_km[1];
        unsigned base = ((unsigned)row) << 9;
#pragma unroll
        for (int q = 0; q < 4; q++) {
            int k = tid + q * 128;
            unsigned o0, o1;
            tf2x32(km0, km1, 0u, base + (unsigned)k, o0, o1);
            float u = bits_to_unit(o0 ^ o1);
            const float df = 1.3f - 0.7f;
            float m = fmaxf(0.7f, fmaf(u, df, 0.7f));
            v[q] = am[i * AD + k] * m;
        }
    } else {
        int r1 = (int)g_r1[b * HH + h], r2 = (int)g_r2[b * HH + h];
#pragma unroll
        for (int q = 0; q < 4; q++) {
            int k = tid + q * 128;
            int src = i;
            if (k >= CROSS_C) {
                if (i == r1) src = r2;
                else if (i == r2) src = r1;
            }
            v[q] = am[src * AD + k];
        }
    }

    float mx = fmaxf(fmaxf(v[0], v[1]), fmaxf(v[2], v[3]));
#pragma unroll
    for (int o = 16; o; o >>= 1) mx = fmaxf(mx, __shfl_xor_sync(~0u, mx, o));
    __shared__ float smx[4], ssum[4], sdot[4];
    int wid = tid >> 5, lane = tid & 31;
    if (lane == 0) smx[wid] = mx;
    __syncthreads();
    mx = fmaxf(fmaxf(smx[0], smx[1]), fmaxf(smx[2], smx[3]));

    float s = 0.f, d = 0.f;
    const float* Vb = g_Vp + b * AD;
#pragma unroll
    for (int q = 0; q < 4; q++) {
        float e = expf(v[q] - mx);
        s += e;
        d += e * Vb[tid + q * 128];
    }
#pragma unroll
    for (int o = 16; o; o >>= 1) {
        s += __shfl_xor_sync(~0u, s, o);
        d += __shfl_xor_sync(~0u, d, o);
    }
    if (lane == 0) { ssum[wid] = s; sdot[wid] = d; }
    __syncthreads();
    if (tid == 0) {
        float S = ssum[0] + ssum[1] + ssum[2] + ssum[3];
        float D = sdot[0] + sdot[1] + sdot[2] + sdot[3];
        g_att[b * (HH * AD) + h * AD + i] = D / S;
    }
}

// ---------------- out = att(16,4096) @ WO_w(512,4096)^T + WO_b ----------------
__global__ __launch_bounds__(256) void outproj(const float* __restrict__ Ww,
                                               const float* __restrict__ Wb,
                                               float* __restrict__ out) {
    __shared__ float arow[HH * AD];   // 16 KB
    int b = blockIdx.x;
    for (int m = threadIdx.x; m < HH * AD; m += 256)
        arow[m] = g_att[b * HH * AD + m];
    __syncthreads();
    int wid = threadIdx.x >> 5, lane = threadIdx.x & 31;
    const float4* ar = (const float4*)arow;
#pragma unroll
    for (int l = 0; l < 8; l++) {
        int n = blockIdx.y * 64 + wid * 8 + l;
        const float4* wr = (const float4*)(Ww + (size_t)n * (HH * AD));
        float s = 0.f;
        for (int m = lane; m < (HH * AD) / 4; m += 32) {
            float4 w = wr[m], a = ar[m];
            s += w.x * a.x + w.y * a.y + w.z * a.z + w.w * a.w;
        }
#pragma unroll
        for (int o = 16; o; o >>= 1) s += __shfl_xor_sync(~0u, s, o);
        if (lane == 0) out[b * AD + n] = s + Wb[n];
    }
}

// ---------------- launch ----------------
extern "C" void kernel_launch(void* const* d_in, const int* in_sizes, int n_in,
                              void* d_out, int out_size) {
    const float* Q   = (const float*)d_in[0];
    const float* K   = (const float*)d_in[1];
    const float* V   = (const float*)d_in[2];
    const float* WQw = (const float*)d_in[3];
    const float* WQb = (const float*)d_in[4];
    const float* WKw = (const float*)d_in[5];
    const float* WKb = (const float*)d_in[6];
    const float* WVw = (const float*)d_in[7];
    const float* WVb = (const float*)d_in[8];
    const float* WOw = (const float*)d_in[9];
    const float* WOb = (const float*)d_in[10];
    float* out = (float*)d_out;

    rng_init<<<1, 128>>>();
    proj_kernel<<<dim3(4, 4, 32), 256>>>(Q, K, WQw, WQb, WKw, WKb);
    vproj<<<dim3(BB, 16), 256>>>(V, WVw, WVb);
    scores_kernel<<<dim3(4, 4, 16), 256>>>();
    attn_kernel<<<BB * HH * AD, 128>>>();
    outproj<<<dim3(BB, 8), 256>>>(WOw, WOb, out);
}